// round 1
// baseline (speedup 1.0000x reference)
#include <cuda_runtime.h>
#include <math.h>

#define BDIM   2
#define LDIM   2048
#define DMODEL 1024
#define DINNER 2048
#define DSTATE 16
#define DTRANK 64
#define DCONV  4
#define NROWS  (BDIM * LDIM)   // 4096
#define XDBLW  (DTRANK + 2 * DSTATE)  // 96

// ---------------- scratch (static device globals; no allocation) ----------------
__device__ __align__(16) float g_xz  [(size_t)NROWS * 2 * DINNER];  // 64 MB  in_proj out (xs_raw | z)
__device__ __align__(16) float g_xs  [(size_t)NROWS * DINNER];      // 32 MB  conv+silu out
__device__ __align__(16) float g_xdbl[(size_t)NROWS * XDBLW];       // 1.5 MB x_proj out (dt_lr | B | C)
__device__ __align__(16) float g_dt  [(size_t)NROWS * DINNER];      // 32 MB  softplus(dt)
__device__ __align__(16) float g_A   [DINNER * DSTATE];             // A = -exp(A_log)
__device__ __align__(16) float g_y   [(size_t)NROWS * DINNER];      // 32 MB  gated scan output

// ---------------- fused epilogues ----------------
__device__ __forceinline__ float softplus_f(float v) {
    return v > 20.f ? v : log1pf(expf(v));
}

// ---------------- generic C = A(M,K) * W(N,K)^T GEMM ----------------
// fp32, 128x128 tile, BK=8, 256 threads, 8x8 microtile.
// EPI: 0 = none, 1 = softplus(acc + bias[n])
template<int EPI>
__global__ __launch_bounds__(256) void gemm_tn(
    const float* __restrict__ A, int lda,
    const float* __restrict__ W, int ldw,
    float* __restrict__ C, int ldc,
    int M, int N, int K,
    const float* __restrict__ bias)
{
    __shared__ __align__(16) float As[8][128];
    __shared__ __align__(16) float Ws[8][128];

    const int tid   = threadIdx.x;
    const int mBase = blockIdx.y * 128;
    const int nBase = blockIdx.x * 128;
    const int tx = tid & 15;
    const int ty = tid >> 4;
    const int lRow = tid >> 1;        // 0..127
    const int lK   = (tid & 1) * 4;   // 0 or 4

    float acc[8][8];
#pragma unroll
    for (int i = 0; i < 8; i++)
#pragma unroll
        for (int j = 0; j < 8; j++) acc[i][j] = 0.f;

    const bool aOk = (mBase + lRow) < M;
    const bool wOk = (nBase + lRow) < N;
    const float* Aptr = A + (size_t)(mBase + lRow) * lda + lK;
    const float* Wptr = W + (size_t)(nBase + lRow) * ldw + lK;

    for (int k0 = 0; k0 < K; k0 += 8) {
        float4 av = make_float4(0.f, 0.f, 0.f, 0.f);
        float4 wv = make_float4(0.f, 0.f, 0.f, 0.f);
        if (aOk) av = *(const float4*)(Aptr + k0);
        if (wOk) wv = *(const float4*)(Wptr + k0);

        __syncthreads();
        As[lK + 0][lRow] = av.x;
        As[lK + 1][lRow] = av.y;
        As[lK + 2][lRow] = av.z;
        As[lK + 3][lRow] = av.w;
        Ws[lK + 0][lRow] = wv.x;
        Ws[lK + 1][lRow] = wv.y;
        Ws[lK + 2][lRow] = wv.z;
        Ws[lK + 3][lRow] = wv.w;
        __syncthreads();

#pragma unroll
        for (int kk = 0; kk < 8; kk++) {
            float4 a0 = *(const float4*)&As[kk][ty * 8];
            float4 a1 = *(const float4*)&As[kk][ty * 8 + 4];
            float4 w0 = *(const float4*)&Ws[kk][tx * 8];
            float4 w1 = *(const float4*)&Ws[kk][tx * 8 + 4];
            float ar[8] = {a0.x, a0.y, a0.z, a0.w, a1.x, a1.y, a1.z, a1.w};
            float wr[8] = {w0.x, w0.y, w0.z, w0.w, w1.x, w1.y, w1.z, w1.w};
#pragma unroll
            for (int i = 0; i < 8; i++)
#pragma unroll
                for (int j = 0; j < 8; j++)
                    acc[i][j] += ar[i] * wr[j];
        }
    }

#pragma unroll
    for (int i = 0; i < 8; i++) {
        const int m = mBase + ty * 8 + i;
        if (m >= M) continue;
#pragma unroll
        for (int jj = 0; jj < 2; jj++) {
            const int col = nBase + tx * 8 + jj * 4;
            if (col >= N) continue;   // N is a multiple of 4 in all uses
            float4 v;
            v.x = acc[i][jj * 4 + 0];
            v.y = acc[i][jj * 4 + 1];
            v.z = acc[i][jj * 4 + 2];
            v.w = acc[i][jj * 4 + 3];
            if (EPI == 1) {
                v.x = softplus_f(v.x + bias[col + 0]);
                v.y = softplus_f(v.y + bias[col + 1]);
                v.z = softplus_f(v.z + bias[col + 2]);
                v.w = softplus_f(v.w + bias[col + 3]);
            }
            *(float4*)&C[(size_t)m * ldc + col] = v;
        }
    }
}

// ---------------- causal depthwise conv (k=4) + bias + SiLU ----------------
// reads xs_raw = g_xz[:, 0:DINNER], writes g_xs
__global__ __launch_bounds__(256) void conv_silu_kernel(
    const float* __restrict__ cw, const float* __restrict__ cb)
{
    const int r = blockIdx.x;         // 0..NROWS-1 : (b, l)
    const int b = r / LDIM;
    const int l = r % LDIM;
    for (int d = threadIdx.x; d < DINNER; d += blockDim.x) {
        float acc = cb[d];
#pragma unroll
        for (int j = 0; j < DCONV; j++) {
            const int lj = l - (DCONV - 1) + j;
            if (lj >= 0)
                acc += cw[d * DCONV + j] * g_xz[(size_t)(b * LDIM + lj) * (2 * DINNER) + d];
        }
        const float s = acc / (1.f + expf(-acc));   // SiLU
        g_xs[(size_t)r * DINNER + d] = s;
    }
}

// ---------------- A = -exp(A_log) ----------------
__global__ void prep_A_kernel(const float* __restrict__ A_log)
{
    const int i = blockIdx.x * blockDim.x + threadIdx.x;
    if (i < DINNER * DSTATE) g_A[i] = -expf(A_log[i]);
}

// ---------------- selective scan + D skip + SiLU(z) gate ----------------
// one thread per (b, d) channel, 16 states in registers
__global__ __launch_bounds__(128) void scan_kernel(const float* __restrict__ Dvec)
{
    const int b = blockIdx.y;
    const int d = blockIdx.x * 128 + threadIdx.x;

    __shared__ float Bsh[32][DSTATE];
    __shared__ float Csh[32][DSTATE];

    float a[DSTATE], h[DSTATE];
#pragma unroll
    for (int n = 0; n < DSTATE; n++) {
        a[n] = g_A[d * DSTATE + n];
        h[n] = 0.f;
    }
    const float Dd = Dvec[d];
    const size_t rowBase = (size_t)b * LDIM;

    for (int t0 = 0; t0 < LDIM; t0 += 32) {
        __syncthreads();
        // stage B,C for the next 32 timesteps
        for (int i = threadIdx.x; i < 32 * 32; i += 128) {
            const int tl = i >> 5;
            const int c  = i & 31;
            const float v = g_xdbl[(rowBase + t0 + tl) * XDBLW + DTRANK + c];
            if (c < DSTATE) Bsh[tl][c] = v;
            else            Csh[tl][c - DSTATE] = v;
        }
        __syncthreads();

        for (int tl = 0; tl < 32; tl++) {
            const size_t r = rowBase + t0 + tl;
            const float dt = g_dt[r * DINNER + d];
            const float x  = g_xs[r * DINNER + d];
            const float z  = g_xz[r * (2 * DINNER) + DINNER + d];
            const float dtx = dt * x;
            float y = 0.f;
#pragma unroll
            for (int n = 0; n < DSTATE; n++) {
                const float dA = __expf(dt * a[n]);
                h[n] = h[n] * dA + dtx * Bsh[tl][n];
                y += h[n] * Csh[tl][n];
            }
            y += Dd * x;
            const float sz = z / (1.f + __expf(-z));  // SiLU gate
            g_y[r * DINNER + d] = y * sz;
        }
    }
}

// ---------------- launch ----------------
extern "C" void kernel_launch(void* const* d_in, const int* in_sizes, int n_in,
                              void* d_out, int out_size)
{
    const float* x       = (const float*)d_in[0];   // [B,L,1024]
    const float* W_in    = (const float*)d_in[1];   // [4096,1024]
    const float* conv_w  = (const float*)d_in[2];   // [2048,1,4]
    const float* conv_b  = (const float*)d_in[3];   // [2048]
    const float* W_xproj = (const float*)d_in[4];   // [96,2048]
    const float* W_dt    = (const float*)d_in[5];   // [2048,64]
    const float* b_dt    = (const float*)d_in[6];   // [2048]
    const float* A_log   = (const float*)d_in[7];   // [2048,16]
    const float* Dvec    = (const float*)d_in[8];   // [2048]
    const float* W_out   = (const float*)d_in[9];   // [1024,2048]
    float* out = (float*)d_out;                     // [B,L,1024]

    float *xz, *xs, *xdbl, *dtb, *y;
    cudaGetSymbolAddress((void**)&xz,   g_xz);
    cudaGetSymbolAddress((void**)&xs,   g_xs);
    cudaGetSymbolAddress((void**)&xdbl, g_xdbl);
    cudaGetSymbolAddress((void**)&dtb,  g_dt);
    cudaGetSymbolAddress((void**)&y,    g_y);

    // 1. in_proj: xz = x @ W_in^T   [4096 x 4096], K=1024
    gemm_tn<0><<<dim3(4096 / 128, NROWS / 128), 256>>>(
        x, DMODEL, W_in, DMODEL, xz, 2 * DINNER, NROWS, 2 * DINNER, DMODEL, nullptr);

    // 2. conv + SiLU on xs half
    conv_silu_kernel<<<NROWS, 256>>>(conv_w, conv_b);

    // 3. x_proj: x_dbl = xs @ W_xproj^T   [4096 x 96], K=2048
    gemm_tn<0><<<dim3(1, NROWS / 128), 256>>>(
        xs, DINNER, W_xproj, DINNER, xdbl, XDBLW, NROWS, XDBLW, DINNER, nullptr);

    // 4. dt = softplus(x_dbl[:, :64] @ W_dt^T + b_dt)   [4096 x 2048], K=64
    gemm_tn<1><<<dim3(DINNER / 128, NROWS / 128), 256>>>(
        xdbl, XDBLW, W_dt, DTRANK, dtb, DINNER, NROWS, DINNER, DTRANK, b_dt);

    // 5. A = -exp(A_log)
    prep_A_kernel<<<(DINNER * DSTATE + 255) / 256, 256>>>(A_log);

    // 6. selective scan + D skip + gate
    scan_kernel<<<dim3(DINNER / 128, BDIM), 128>>>(Dvec);

    // 7. out_proj: out = y @ W_out^T   [4096 x 1024], K=2048
    gemm_tn<0><<<dim3(DMODEL / 128, NROWS / 128), 256>>>(
        y, DINNER, W_out, DINNER, out, DMODEL, NROWS, DMODEL, DINNER, nullptr);
}

// round 2
// speedup vs baseline: 1.2337x; 1.2337x over previous
#include <cuda_runtime.h>
#include <cuda_bf16.h>
#include <math.h>

#define BDIM   2
#define LDIM   2048
#define DMODEL 1024
#define DINNER 2048
#define DSTATE 16
#define DTRANK 64
#define DCONV  4
#define NROWS  (BDIM * LDIM)          // 4096
#define XDBLW  (DTRANK + 2 * DSTATE)  // 96

// ---------------- scratch (static device globals; no allocation) ----------------
__device__ __align__(16) float g_xz  [(size_t)NROWS * 2 * DINNER];  // in_proj out (xs_raw | z)
__device__ __align__(16) float g_xs  [(size_t)NROWS * DINNER];      // conv+silu out
__device__ __align__(16) float g_xdbl[(size_t)NROWS * XDBLW];       // x_proj out (dt_lr | B | C)
__device__ __align__(16) float g_dt  [(size_t)NROWS * DINNER];      // softplus(dt)
__device__ __align__(16) float g_y   [(size_t)NROWS * DINNER];      // gated scan output

__device__ __forceinline__ float softplus_f(float v) {
    return v > 20.f ? v : log1pf(expf(v));
}

__device__ __forceinline__ unsigned pack_bf2(__nv_bfloat16 a, __nv_bfloat16 b) {
    __nv_bfloat162 t = __halves2bfloat162(a, b);
    return *reinterpret_cast<unsigned*>(&t);
}

__device__ __forceinline__ void mma16816(float* c, const unsigned* a, const unsigned* b) {
    asm volatile(
        "mma.sync.aligned.m16n8k16.row.col.f32.bf16.bf16.f32 "
        "{%0,%1,%2,%3}, {%4,%5,%6,%7}, {%8,%9}, {%0,%1,%2,%3};\n"
        : "+f"(c[0]), "+f"(c[1]), "+f"(c[2]), "+f"(c[3])
        : "r"(a[0]), "r"(a[1]), "r"(a[2]), "r"(a[3]), "r"(b[0]), "r"(b[1]));
}

// ============ C = A(M,K) * W(N,K)^T, tensor-core bf16 split-2 (3 MMAs) ============
// BM x 128 tile, BK=32, 256 threads (8 warps: 2 rows x 4 cols), double-buffered.
// EPI: 0 = none, 1 = softplus(acc + bias[col])
template<int BM, int EPI>
__global__ __launch_bounds__(256) void gemm_mma(
    const float* __restrict__ A, int lda,
    const float* __restrict__ W, int ldw,
    float* __restrict__ C, int ldc,
    int M, int N, int K,
    const float* __restrict__ bias)
{
    constexpr int ITILES = BM / 32;        // 16-row m-tiles per warp
    constexpr int LIT    = BM / 32;        // loader iterations for A
    constexpr int BKP    = 40;             // padded bf16 row length (conflict-free)
    constexpr int ASZ    = BM  * BKP;
    constexpr int WSZ    = 128 * BKP;
    constexpr int BUF    = 2 * ASZ + 2 * WSZ;  // bf16 elems per buffer

    extern __shared__ __align__(16) __nv_bfloat16 sm[];

    const int tid  = threadIdx.x;
    const int lane = tid & 31;
    const int warp = tid >> 5;
    const int wr = warp >> 2;     // 0..1
    const int wc = warp & 3;      // 0..3
    const int g  = lane >> 2;     // 0..7
    const int tg = lane & 3;      // 0..3

    const int mBase = blockIdx.y * BM;
    const int nBase = blockIdx.x * 128;

    const int ldRow = tid >> 3;         // 0..31
    const int ldCol = (tid & 7) << 2;   // 0,4,...,28

    float acc[ITILES][4][4];
#pragma unroll
    for (int i = 0; i < ITILES; i++)
#pragma unroll
        for (int j = 0; j < 4; j++)
#pragma unroll
            for (int e = 0; e < 4; e++) acc[i][j][e] = 0.f;

    float4 ra[LIT], rw[4];

    auto load_g = [&](int k0) {
#pragma unroll
        for (int it = 0; it < LIT; it++) {
            int r = ldRow + it * 32;
            ra[it] = *(const float4*)&A[(size_t)(mBase + r) * lda + k0 + ldCol];
        }
#pragma unroll
        for (int it = 0; it < 4; it++) {
            int nr = nBase + ldRow + it * 32;
            rw[it] = (nr < N) ? *(const float4*)&W[(size_t)nr * ldw + k0 + ldCol]
                              : make_float4(0.f, 0.f, 0.f, 0.f);
        }
    };

    auto store_s = [&](int bufIdx) {
        __nv_bfloat16* Ah = sm + bufIdx * BUF;
        __nv_bfloat16* Al = Ah + ASZ;
        __nv_bfloat16* Wh = Al + ASZ;
        __nv_bfloat16* Wl = Wh + WSZ;
#pragma unroll
        for (int it = 0; it < LIT; it++) {
            int r = ldRow + it * 32;
            float v[4] = {ra[it].x, ra[it].y, ra[it].z, ra[it].w};
            __nv_bfloat16 h[4], l[4];
#pragma unroll
            for (int e = 0; e < 4; e++) {
                h[e] = __float2bfloat16(v[e]);
                l[e] = __float2bfloat16(v[e] - __bfloat162float(h[e]));
            }
            uint2 uh = make_uint2(pack_bf2(h[0], h[1]), pack_bf2(h[2], h[3]));
            uint2 ul = make_uint2(pack_bf2(l[0], l[1]), pack_bf2(l[2], l[3]));
            *(uint2*)&Ah[r * BKP + ldCol] = uh;
            *(uint2*)&Al[r * BKP + ldCol] = ul;
        }
#pragma unroll
        for (int it = 0; it < 4; it++) {
            int r = ldRow + it * 32;
            float v[4] = {rw[it].x, rw[it].y, rw[it].z, rw[it].w};
            __nv_bfloat16 h[4], l[4];
#pragma unroll
            for (int e = 0; e < 4; e++) {
                h[e] = __float2bfloat16(v[e]);
                l[e] = __float2bfloat16(v[e] - __bfloat162float(h[e]));
            }
            uint2 uh = make_uint2(pack_bf2(h[0], h[1]), pack_bf2(h[2], h[3]));
            uint2 ul = make_uint2(pack_bf2(l[0], l[1]), pack_bf2(l[2], l[3]));
            *(uint2*)&Wh[r * BKP + ldCol] = uh;
            *(uint2*)&Wl[r * BKP + ldCol] = ul;
        }
    };

    auto compute = [&](int bufIdx) {
        const __nv_bfloat16* Ah = sm + bufIdx * BUF;
        const __nv_bfloat16* Al = Ah + ASZ;
        const __nv_bfloat16* Wh = Al + ASZ;
        const __nv_bfloat16* Wl = Wh + WSZ;
#pragma unroll
        for (int ks = 0; ks < 2; ks++) {
            const int kb = ks * 16 + 2 * tg;
            unsigned bh[4][2], bl[4][2];
#pragma unroll
            for (int j = 0; j < 4; j++) {
                int n = wc * 32 + j * 8 + g;
                bh[j][0] = *(const unsigned*)&Wh[n * BKP + kb];
                bh[j][1] = *(const unsigned*)&Wh[n * BKP + kb + 8];
                bl[j][0] = *(const unsigned*)&Wl[n * BKP + kb];
                bl[j][1] = *(const unsigned*)&Wl[n * BKP + kb + 8];
            }
#pragma unroll
            for (int i = 0; i < ITILES; i++) {
                int m = wr * (BM / 2) + i * 16 + g;
                unsigned ah[4], al[4];
                ah[0] = *(const unsigned*)&Ah[m * BKP + kb];
                ah[1] = *(const unsigned*)&Ah[(m + 8) * BKP + kb];
                ah[2] = *(const unsigned*)&Ah[m * BKP + kb + 8];
                ah[3] = *(const unsigned*)&Ah[(m + 8) * BKP + kb + 8];
                al[0] = *(const unsigned*)&Al[m * BKP + kb];
                al[1] = *(const unsigned*)&Al[(m + 8) * BKP + kb];
                al[2] = *(const unsigned*)&Al[m * BKP + kb + 8];
                al[3] = *(const unsigned*)&Al[(m + 8) * BKP + kb + 8];
#pragma unroll
                for (int j = 0; j < 4; j++) {
                    mma16816(acc[i][j], ah, bh[j]);  // hi * hi
                    mma16816(acc[i][j], al, bh[j]);  // lo * hi
                    mma16816(acc[i][j], ah, bl[j]);  // hi * lo
                }
            }
        }
    };

    load_g(0);
    store_s(0);
    __syncthreads();

    const int nk = K >> 5;
    for (int c = 0; c < nk; c++) {
        if (c + 1 < nk) load_g((c + 1) << 5);
        compute(c & 1);
        if (c + 1 < nk) store_s((c + 1) & 1);
        __syncthreads();
    }

    // epilogue
#pragma unroll
    for (int i = 0; i < ITILES; i++) {
        const int row0 = mBase + wr * (BM / 2) + i * 16 + g;
#pragma unroll
        for (int j = 0; j < 4; j++) {
            const int col = nBase + wc * 32 + j * 8 + 2 * tg;
            if (col < N) {
                float2 v0 = make_float2(acc[i][j][0], acc[i][j][1]);
                float2 v1 = make_float2(acc[i][j][2], acc[i][j][3]);
                if (EPI == 1) {
                    const float b0 = bias[col], b1 = bias[col + 1];
                    v0.x = softplus_f(v0.x + b0);
                    v0.y = softplus_f(v0.y + b1);
                    v1.x = softplus_f(v1.x + b0);
                    v1.y = softplus_f(v1.y + b1);
                }
                *(float2*)&C[(size_t)row0 * ldc + col] = v0;
                *(float2*)&C[(size_t)(row0 + 8) * ldc + col] = v1;
            }
        }
    }
}

// ---------------- causal depthwise conv (k=4) + bias + SiLU ----------------
// one thread per channel, sliding window over an L-chunk; exact traffic
#define CONV_LT 128
__global__ __launch_bounds__(256) void conv_silu_kernel(
    const float* __restrict__ cw, const float* __restrict__ cb)
{
    const int d  = blockIdx.x * 256 + threadIdx.x;
    const int b  = blockIdx.z;
    const int l0 = blockIdx.y * CONV_LT;

    const float w0 = cw[d * 4 + 0], w1 = cw[d * 4 + 1];
    const float w2 = cw[d * 4 + 2], w3 = cw[d * 4 + 3];
    const float bias = cb[d];

    const float* xp = g_xz + (size_t)b * LDIM * (2 * DINNER) + d;
    float xm3 = (l0 - 3 >= 0) ? xp[(size_t)(l0 - 3) * (2 * DINNER)] : 0.f;
    float xm2 = (l0 - 2 >= 0) ? xp[(size_t)(l0 - 2) * (2 * DINNER)] : 0.f;
    float xm1 = (l0 - 1 >= 0) ? xp[(size_t)(l0 - 1) * (2 * DINNER)] : 0.f;

    for (int l = l0; l < l0 + CONV_LT; l++) {
        const float xc = xp[(size_t)l * (2 * DINNER)];
        const float acc = bias + w0 * xm3 + w1 * xm2 + w2 * xm1 + w3 * xc;
        const float s = acc / (1.f + __expf(-acc));
        g_xs[((size_t)b * LDIM + l) * DINNER + d] = s;
        xm3 = xm2; xm2 = xm1; xm1 = xc;
    }
}

// ---------------- selective scan + D skip + SiLU(z) gate ----------------
// 4 threads per (b,d) channel, 4 states each; A prep fused
__global__ __launch_bounds__(128) void scan_kernel(
    const float* __restrict__ A_log, const float* __restrict__ Dvec)
{
    const int b    = blockIdx.y;
    const int tid  = threadIdx.x;
    const int sub  = tid & 3;        // state group
    const int dloc = tid >> 2;       // 0..31
    const int d    = blockIdx.x * 32 + dloc;
    const int n0   = sub * 4;

    __shared__ float Bsh[32][DSTATE];
    __shared__ float Csh[32][DSTATE];

    float a[4], h[4];
#pragma unroll
    for (int n = 0; n < 4; n++) {
        a[n] = -__expf(A_log[d * DSTATE + n0 + n]);
        h[n] = 0.f;
    }
    const float Dd = Dvec[d];
    const size_t rowBase = (size_t)b * LDIM;

    for (int t0 = 0; t0 < LDIM; t0 += 32) {
        __syncthreads();
        for (int i = tid; i < 32 * 32; i += 128) {
            const int tl = i >> 5;
            const int c  = i & 31;
            const float v = g_xdbl[(rowBase + t0 + tl) * XDBLW + DTRANK + c];
            if (c < DSTATE) Bsh[tl][c] = v;
            else            Csh[tl][c - DSTATE] = v;
        }
        __syncthreads();

#pragma unroll 4
        for (int tl = 0; tl < 32; tl++) {
            const size_t r = rowBase + t0 + tl;
            const float dt = g_dt[r * DINNER + d];
            const float x  = g_xs[r * DINNER + d];
            const float z  = g_xz[r * (2 * DINNER) + DINNER + d];
            const float dtx = dt * x;
            float y = 0.f;
#pragma unroll
            for (int n = 0; n < 4; n++) {
                const float dA = __expf(dt * a[n]);
                h[n] = h[n] * dA + dtx * Bsh[tl][n0 + n];
                y += h[n] * Csh[tl][n0 + n];
            }
            y += __shfl_xor_sync(0xffffffffu, y, 1);
            y += __shfl_xor_sync(0xffffffffu, y, 2);
            y += Dd * x;
            const float sz = z / (1.f + __expf(-z));
            if (sub == 0) g_y[r * DINNER + d] = y * sz;
        }
    }
}

// ---------------- launch ----------------
extern "C" void kernel_launch(void* const* d_in, const int* in_sizes, int n_in,
                              void* d_out, int out_size)
{
    const float* x       = (const float*)d_in[0];   // [B,L,1024]
    const float* W_in    = (const float*)d_in[1];   // [4096,1024]
    const float* conv_w  = (const float*)d_in[2];   // [2048,1,4]
    const float* conv_b  = (const float*)d_in[3];   // [2048]
    const float* W_xproj = (const float*)d_in[4];   // [96,2048]
    const float* W_dt    = (const float*)d_in[5];   // [2048,64]
    const float* b_dt    = (const float*)d_in[6];   // [2048]
    const float* A_log   = (const float*)d_in[7];   // [2048,16]
    const float* Dvec    = (const float*)d_in[8];   // [2048]
    const float* W_out   = (const float*)d_in[9];   // [1024,2048]
    float* out = (float*)d_out;                     // [B,L,1024]

    float *xz, *xs, *xdbl, *dtb, *y;
    cudaGetSymbolAddress((void**)&xz,   g_xz);
    cudaGetSymbolAddress((void**)&xs,   g_xs);
    cudaGetSymbolAddress((void**)&xdbl, g_xdbl);
    cudaGetSymbolAddress((void**)&dtb,  g_dt);
    cudaGetSymbolAddress((void**)&y,    g_y);

    constexpr int SM128 = (2 * 128 * 40 + 2 * 128 * 40) * 2 * 2;  // 81920 B
    constexpr int SM32  = (2 * 32  * 40 + 2 * 128 * 40) * 2 * 2;  // 51200 B
    cudaFuncSetAttribute((const void*)gemm_mma<128, 0>,
                         cudaFuncAttributeMaxDynamicSharedMemorySize, SM128);
    cudaFuncSetAttribute((const void*)gemm_mma<128, 1>,
                         cudaFuncAttributeMaxDynamicSharedMemorySize, SM128);
    cudaFuncSetAttribute((const void*)gemm_mma<32, 0>,
                         cudaFuncAttributeMaxDynamicSharedMemorySize, SM32);

    // 1. in_proj: xz = x @ W_in^T   [4096 x 4096], K=1024
    gemm_mma<128, 0><<<dim3(4096 / 128, NROWS / 128), 256, SM128>>>(
        x, DMODEL, W_in, DMODEL, xz, 2 * DINNER, NROWS, 2 * DINNER, DMODEL, nullptr);

    // 2. conv + SiLU
    conv_silu_kernel<<<dim3(DINNER / 256, LDIM / CONV_LT, BDIM), 256>>>(conv_w, conv_b);

    // 3. x_proj: x_dbl = xs @ W_xproj^T   [4096 x 96], K=2048 (BM=32 for parallelism)
    gemm_mma<32, 0><<<dim3(1, NROWS / 32), 256, SM32>>>(
        xs, DINNER, W_xproj, DINNER, xdbl, XDBLW, NROWS, XDBLW, DINNER, nullptr);

    // 4. dt = softplus(x_dbl[:, :64] @ W_dt^T + b_dt)   [4096 x 2048], K=64
    gemm_mma<128, 1><<<dim3(DINNER / 128, NROWS / 128), 256, SM128>>>(
        xdbl, XDBLW, W_dt, DTRANK, dtb, DINNER, NROWS, DINNER, DTRANK, b_dt);

    // 5. selective scan + D skip + gate (A prep fused)
    scan_kernel<<<dim3(DINNER / 32, BDIM), 128>>>(A_log, Dvec);

    // 6. out_proj: out = y @ W_out^T   [4096 x 1024], K=2048
    gemm_mma<128, 0><<<dim3(DMODEL / 128, NROWS / 128), 256, SM128>>>(
        y, DINNER, W_out, DINNER, out, DMODEL, NROWS, DMODEL, DINNER, nullptr);
}